// round 10
// baseline (speedup 1.0000x reference)
#include <cuda_runtime.h>
#include <cuda_bf16.h>
#include <math.h>

// FusionHead fully fused, fp32 + packed f32x2 FMA.
// R7: weight repacking. A per-launch repack kernel rewrites the five big GEMM
// stage weights into per-(warp,k-iter) consumption order so every weight
// LDG.128's four lane addresses are contiguous 64B (1 wavefront instead of 4).
// R5 was L1-bound at 89.5% with fma 43.3% because each weight load touched 4
// cache lines 4608B apart.

#define D 192
#define ROWS 16           // batch rows per CTA
#define TOK 32            // token rows per CTA
#define THREADS 256
#define LDA 196           // SA pitch (words): /4 = 49 (odd) -> conflict-free
#define LDB 580           // SB pitch (words): /4 = 145 (odd)

// packed weight segments (float4 units)
#define PK_WP   0
#define PK_WT   9216
#define PK_IN   18432
#define PK_OUT  46080
#define PK_F1   55296
#define PK_F2   73728
#define PK_TOTAL 92160    // 1.47 MB

__device__ float4 g_pack[PK_TOTAL];

typedef unsigned long long u64;

__device__ __forceinline__ void fma2(u64 &d, const u64 a, const u64 b) {
    asm("fma.rn.f32x2 %0, %1, %2, %0;" : "+l"(d) : "l"(a), "l"(b));
}
__device__ __forceinline__ float hsum2(const u64 v) {
    float lo, hi;
    asm("mov.b64 {%0, %1}, %2;" : "=f"(lo), "=f"(hi) : "l"(v));
    return lo + hi;
}
__device__ __forceinline__ u64 pack2(const float lo, const float hi) {
    u64 r;
    asm("mov.b64 %0, {%1, %2};" : "=l"(r) : "f"(lo), "f"(hi));
    return r;
}

// ---------------------------------------------------------------------------
// Repack kernel: g_pack[(pw*K4 + k)*24 + j*4 + cs] = W[c][4k..4k+3],
//   c = pw*24 + cs*6 + j   (pw = pass*8 + warp; pass block = 192 cols)
// ---------------------------------------------------------------------------
__global__ void repack_kernel(
    const float* __restrict__ Wp, const float* __restrict__ Wt,
    const float* __restrict__ in_w, const float* __restrict__ out_w,
    const float* __restrict__ ffn_w1, const float* __restrict__ ffn_w2)
{
    const int i = blockIdx.x * blockDim.x + threadIdx.x;
    if (i >= PK_TOTAL) return;
    const float* src;
    int K4, rel;
    if      (i < PK_WT)  { src = Wp;     K4 = 48; rel = i - PK_WP;  }
    else if (i < PK_IN)  { src = Wt;     K4 = 48; rel = i - PK_WT;  }
    else if (i < PK_OUT) { src = in_w;   K4 = 48; rel = i - PK_IN;  }
    else if (i < PK_F1)  { src = out_w;  K4 = 48; rel = i - PK_OUT; }
    else if (i < PK_F2)  { src = ffn_w1; K4 = 48; rel = i - PK_F1;  }
    else                 { src = ffn_w2; K4 = 96; rel = i - PK_F2;  }
    const int t  = rel % 24;
    const int cs = t & 3, j = t >> 2;
    const int rk = rel / 24;
    const int k  = rk % K4;
    const int pw = rk / K4;
    const int c  = pw * 24 + cs * 6 + j;
    g_pack[i] = reinterpret_cast<const float4*>(src)[(size_t)c * K4 + k];
}

// ---------------------------------------------------------------------------
// 4-row x 6-col register tile GEMM, packed weights.
//   pw01/pw23: packed weight base for this (pass,warp): g_pack + seg + pw*K4*24
//   rows {rg, rg+8, rg+16, rg+24}; cols c0..c0+? (c0 = cb + warp*24 + cs*6)
// ---------------------------------------------------------------------------
template<int K4, bool RELU, bool DUAL, bool RES>
__device__ __forceinline__ void gemm_tile(
    const float4* __restrict__ pw01, const float4* __restrict__ pw23,
    const float* __restrict__ b01, const float* __restrict__ b23,
    const float* __restrict__ Asm, int ldaw,
    float* __restrict__ Osm, int ldow,
    const float* __restrict__ Rsm, int ldrw,
    int c0, int cs, int rg)
{
    u64 acc[4][6];
    #pragma unroll
    for (int i = 0; i < 4; i++)
        #pragma unroll
        for (int j = 0; j < 6; j++) acc[i][j] = 0ULL;

    const float4* __restrict__ a0 = reinterpret_cast<const float4*>(Asm + rg * ldaw);
    const float4* __restrict__ a1 = reinterpret_cast<const float4*>(Asm + (rg + 8) * ldaw);
    const float4* __restrict__ a2 = reinterpret_cast<const float4*>(Asm + (rg + 16) * ldaw);
    const float4* __restrict__ a3 = reinterpret_cast<const float4*>(Asm + (rg + 24) * ldaw);

    #pragma unroll 2
    for (int k = 0; k < K4; k++) {
        const float4 av0 = a0[k], av1 = a1[k], av2 = a2[k], av3 = a3[k];
        const u64 lo0 = pack2(av0.x, av0.y), hi0 = pack2(av0.z, av0.w);
        const u64 lo1 = pack2(av1.x, av1.y), hi1 = pack2(av1.z, av1.w);
        const u64 lo2 = pack2(av2.x, av2.y), hi2 = pack2(av2.z, av2.w);
        const u64 lo3 = pack2(av3.x, av3.y), hi3 = pack2(av3.z, av3.w);
        const int kb = k * 24 + cs;
        #pragma unroll
        for (int j = 0; j < 6; j++) {
            const float4 w = pw01[kb + j * 4];
            const u64 wlo = pack2(w.x, w.y), whi = pack2(w.z, w.w);
            fma2(acc[0][j], lo0, wlo); fma2(acc[0][j], hi0, whi);
            fma2(acc[1][j], lo1, wlo); fma2(acc[1][j], hi1, whi);
            u64 wlo2, whi2;
            if (DUAL) {
                const float4 w2 = pw23[kb + j * 4];
                wlo2 = pack2(w2.x, w2.y); whi2 = pack2(w2.z, w2.w);
            } else { wlo2 = wlo; whi2 = whi; }
            fma2(acc[2][j], lo2, wlo2); fma2(acc[2][j], hi2, whi2);
            fma2(acc[3][j], lo3, wlo2); fma2(acc[3][j], hi3, whi2);
        }
    }

    #pragma unroll
    for (int j = 0; j < 6; j++) {
        const int c = c0 + j;
        float v0 = hsum2(acc[0][j]) + b01[c];
        float v1 = hsum2(acc[1][j]) + b01[c];
        float v2 = hsum2(acc[2][j]) + b23[c];
        float v3 = hsum2(acc[3][j]) + b23[c];
        if (RES) {
            v0 += Rsm[rg * ldrw + c];
            v1 += Rsm[(rg + 8) * ldrw + c];
            v2 += Rsm[(rg + 16) * ldrw + c];
            v3 += Rsm[(rg + 24) * ldrw + c];
        }
        if (RELU) {
            v0 = fmaxf(v0, 0.f); v1 = fmaxf(v1, 0.f);
            v2 = fmaxf(v2, 0.f); v3 = fmaxf(v3, 0.f);
        }
        Osm[rg * ldow + c]        = v0;
        Osm[(rg + 8) * ldow + c]  = v1;
        Osm[(rg + 16) * ldow + c] = v2;
        Osm[(rg + 24) * ldow + c] = v3;
    }
}

// Head-stage GEMM (small): one thread, C cols for one activation row.
template<int C, int K, bool RELU>
__device__ __forceinline__ void gemm_b(
    const float* __restrict__ Wc, const float* __restrict__ biasc,
    const float* __restrict__ Arow,
    float* __restrict__ Orow)
{
    u64 acc[C];
    #pragma unroll
    for (int c = 0; c < C; c++) acc[c] = 0ULL;
    const float4* __restrict__ a4 = reinterpret_cast<const float4*>(Arow);
    #pragma unroll 2
    for (int k = 0; k < (K >> 2); k++) {
        const float4 av = a4[k];
        const u64 alo = pack2(av.x, av.y);
        const u64 ahi = pack2(av.z, av.w);
        #pragma unroll
        for (int c = 0; c < C; c++) {
            const float4 wv = *reinterpret_cast<const float4*>(Wc + c * K + (k << 2));
            fma2(acc[c], alo, pack2(wv.x, wv.y));
            fma2(acc[c], ahi, pack2(wv.z, wv.w));
        }
    }
    #pragma unroll
    for (int c = 0; c < C; c++) {
        float v = hsum2(acc[c]) + biasc[c];
        if (RELU) v = fmaxf(v, 0.f);
        Orow[c] = v;
    }
}

__device__ __forceinline__ void layernorm_rows(
    const float* __restrict__ src, int lds,
    float* __restrict__ dst, int ldd,
    const float* __restrict__ g, const float* __restrict__ b,
    int tid)
{
    const int warp = tid >> 5, lane = tid & 31;
    for (int tr = warp; tr < TOK; tr += 8) {
        const float* x = src + tr * lds;
        float v[6], s = 0.f, sq = 0.f;
        #pragma unroll
        for (int j = 0; j < 6; j++) {
            v[j] = x[lane + 32 * j];
            s += v[j];
            sq += v[j] * v[j];
        }
        #pragma unroll
        for (int o = 16; o; o >>= 1) {
            s  += __shfl_xor_sync(0xffffffffu, s,  o);
            sq += __shfl_xor_sync(0xffffffffu, sq, o);
        }
        const float mean = s * (1.f / 192.f);
        const float var  = sq * (1.f / 192.f) - mean * mean;
        const float rs   = rsqrtf(var + 1e-5f);
        #pragma unroll
        for (int j = 0; j < 6; j++) {
            const int c = lane + 32 * j;
            dst[tr * ldd + c] = (v[j] - mean) * rs * g[c] + b[c];
        }
    }
}

__global__ __launch_bounds__(THREADS, 2)
void fusion_head_kernel(
    const float* __restrict__ perc, const float* __restrict__ tech,
    const float* __restrict__ bp,   const float* __restrict__ bt,
    const float* __restrict__ in_b,
    const float* __restrict__ out_b,
    const float* __restrict__ ffn_b1, const float* __restrict__ ffn_b2,
    const float* __restrict__ ln1_g, const float* __restrict__ ln1_b,
    const float* __restrict__ ln2_g, const float* __restrict__ ln2_b,
    const float* __restrict__ cls_w1, const float* __restrict__ cls_b1,
    const float* __restrict__ cls_w2, const float* __restrict__ cls_b2,
    const float* __restrict__ fp_w,   const float* __restrict__ fp_b,
    float* __restrict__ out, int B)
{
    extern __shared__ float smem[];
    float* SA = smem;                 // [32][LDA] residual / LN stream
    float* SB = smem + TOK * LDA;     // [32][LDB] scratch

    const int tid  = threadIdx.x;
    const int lane = tid & 31;
    const int warp = tid >> 5;
    const int cs   = lane >> 3;       // column subset 0..3
    const int rg   = lane & 7;        // row group 0..7
    const int cbase = warp * 24 + cs * 6;
    const int block0 = blockIdx.x * ROWS;

    // ---- stage 0: stage inputs into SB[tr][0:192] (tr<16: perc, else tech) --
    for (int i = tid; i < TOK * 48; i += THREADS) {
        const int tr = i / 48, k4 = i % 48;
        const int r = (tr < ROWS) ? tr : (tr - ROWS);
        int gr = block0 + r;
        if (gr >= B) gr = B - 1;
        const float* src = (tr < ROWS) ? (perc + (size_t)gr * D)
                                       : (tech + (size_t)gr * D);
        reinterpret_cast<float4*>(SB + tr * LDB)[k4] =
            reinterpret_cast<const float4*>(src)[k4];
    }
    __syncthreads();

    // ---- stage 1: input projections -> SA (rows 0-15: Wp, rows 16-31: Wt) --
    gemm_tile<48, false, true, false>(
        g_pack + PK_WP + warp * 48 * 24, g_pack + PK_WT + warp * 48 * 24,
        bp, bt, SB, LDB, SA, LDA, nullptr, 0, cbase, cs, rg);
    __syncthreads();

    // ---- stage 2: packed QKV -> SB[tr][0:576] (3 column passes) ------------
    #pragma unroll
    for (int p = 0; p < 3; p++) {
        const float4* pw = g_pack + PK_IN + (size_t)(p * 8 + warp) * 48 * 24;
        gemm_tile<48, false, false, false>(pw, pw, in_b, in_b,
                                           SA, LDA, SB, LDB, nullptr, 0,
                                           p * 192 + cbase, cs, rg);
    }
    __syncthreads();

    // ---- stage 3: 2-token, 3-head attention; ctx overwrites q slots --------
    if (tid < ROWS * 6) {
        const int r = tid / 6, rem = tid % 6;
        const int t = rem & 1, h = rem >> 1;
        const float* q  = SB + (t * ROWS + r) * LDB + h * 64;
        const float* k0 = SB + r * LDB + 192 + h * 64;
        const float* k1 = SB + (ROWS + r) * LDB + 192 + h * 64;
        const float* v0 = SB + r * LDB + 384 + h * 64;
        const float* v1 = SB + (ROWS + r) * LDB + 384 + h * 64;
        float s0 = 0.f, s1 = 0.f;
        #pragma unroll 8
        for (int d = 0; d < 64; d++) {
            const float qd = q[d];
            s0 += qd * k0[d];
            s1 += qd * k1[d];
        }
        s0 *= 0.125f; s1 *= 0.125f;
        const float m = fmaxf(s0, s1);
        const float e0 = expf(s0 - m), e1 = expf(s1 - m);
        const float inv = 1.f / (e0 + e1);
        const float a0 = e0 * inv, a1 = e1 * inv;
        float* ctx = SB + (t * ROWS + r) * LDB + h * 64;  // q slot
        #pragma unroll 8
        for (int d = 0; d < 64; d++) ctx[d] = a0 * v0[d] + a1 * v1[d];
    }
    __syncthreads();

    // ---- stage 4: out-proj + residual(SA) -> SB[tr][384:576] ---------------
    {
        const float4* pw = g_pack + PK_OUT + warp * 48 * 24;
        gemm_tile<48, false, false, true>(pw, pw, out_b, out_b,
                                          SB, LDB, SB + 384, LDB, SA, LDA,
                                          cbase, cs, rg);
    }
    __syncthreads();

    // ---- stage 5: LN1 -> SA ------------------------------------------------
    layernorm_rows(SB + 384, LDB, SA, LDA, ln1_g, ln1_b, tid);
    __syncthreads();

    // ---- stage 6: FFN up + ReLU -> SB[tr][0:384] (2 passes) ----------------
    #pragma unroll
    for (int p = 0; p < 2; p++) {
        const float4* pw = g_pack + PK_F1 + (size_t)(p * 8 + warp) * 48 * 24;
        gemm_tile<48, true, false, false>(pw, pw, ffn_b1, ffn_b1,
                                          SA, LDA, SB, LDB, nullptr, 0,
                                          p * 192 + cbase, cs, rg);
    }
    __syncthreads();

    // ---- stage 7: FFN down (K=384) + residual(SA) -> SB[tr][384:576] -------
    {
        const float4* pw = g_pack + PK_F2 + warp * 96 * 24;
        gemm_tile<96, false, false, true>(pw, pw, ffn_b2, ffn_b2,
                                          SB, LDB, SB + 384, LDB, SA, LDA,
                                          cbase, cs, rg);
    }
    __syncthreads();

    // ---- stage 8: LN2 -> SA ------------------------------------------------
    layernorm_rows(SB + 384, LDB, SA, LDA, ln2_g, ln2_b, tid);
    __syncthreads();

    // ---- stage 9: z = mean over 2 tokens -> SB[r][384:576] -----------------
    for (int i = tid; i < ROWS * 48; i += THREADS) {
        const int r = i / 48, k4 = i % 48;
        const float4 x0 = reinterpret_cast<const float4*>(SA + r * LDA)[k4];
        const float4 x1 = reinterpret_cast<const float4*>(SA + (ROWS + r) * LDA)[k4];
        float4 z;
        z.x = 0.5f * (x0.x + x1.x);
        z.y = 0.5f * (x0.y + x1.y);
        z.z = 0.5f * (x0.z + x1.z);
        z.w = 0.5f * (x0.w + x1.w);
        reinterpret_cast<float4*>(SB + r * LDB + 384)[k4] = z;
    }
    __syncthreads();

    // ---- stage 10: heads. row = lane&15, col-half = lane>>4 ----------------
    {
        const int r  = lane & 15;
        const int hf = lane >> 4;
        const float* zrow = SB + r * LDB + 384;
        // cls hidden (relu): 192 cols -> SB[r][0:192]
        {
            const int c0 = warp * 24 + hf * 12;
            gemm_b<12, 192, true>(cls_w1 + c0 * 192, cls_b1 + c0,
                                  zrow, SB + r * LDB + c0);
        }
        // fingerprint: 128 cols -> SB[r][192:320]
        {
            const int c0 = warp * 16 + hf * 8;
            gemm_b<8, 192, false>(fp_w + c0 * 192, fp_b + c0,
                                  zrow, SB + r * LDB + 192 + c0);
        }
    }
    __syncthreads();

    // ---- stage 11: cls logits + sigmoid -> out[j*B + row] ------------------
    if (tid < ROWS * 3) {
        const int r = tid / 3, j = tid % 3;
        const int gr = block0 + r;
        if (gr < B) {
            const float* hrow = SB + r * LDB;
            const float* w = cls_w2 + j * D;
            float s = cls_b2[j];
            #pragma unroll 8
            for (int k = 0; k < D; k++) s += hrow[k] * w[k];
            out[(size_t)j * B + gr] = 1.f / (1.f + expf(-s));
        }
    }

    // ---- stage 12: fingerprint L2-normalize -> out[3B + row*128 + c] -------
    {
        #pragma unroll
        for (int rr = 0; rr < 2; rr++) {
            const int r = warp * 2 + rr;
            const int gr = block0 + r;
            const float* f = SB + r * LDB + 192;
            float v[4], sq = 0.f;
            #pragma unroll
            for (int j = 0; j < 4; j++) {
                v[j] = f[lane + 32 * j];
                sq += v[j] * v[j];
            }
            #pragma unroll
            for (int o = 16; o; o >>= 1)
                sq += __shfl_xor_sync(0xffffffffu, sq, o);
            const float inv = 1.f / fmaxf(sqrtf(sq), 1e-12f);
            if (gr < B) {
                float* o = out + (size_t)3 * B + (size_t)gr * 128;
                #pragma unroll
                for (int j = 0; j < 4; j++) o[lane + 32 * j] = v[j] * inv;
            }
        }
    }
}

extern "C" void kernel_launch(void* const* d_in, const int* in_sizes, int n_in,
                              void* d_out, int out_size)
{
    const float* perc   = (const float*)d_in[0];
    const float* tech   = (const float*)d_in[1];
    const float* Wp     = (const float*)d_in[2];
    const float* bp     = (const float*)d_in[3];
    const float* Wt     = (const float*)d_in[4];
    const float* bt     = (const float*)d_in[5];
    const float* in_w   = (const float*)d_in[6];
    const float* in_b   = (const float*)d_in[7];
    const float* out_w  = (const float*)d_in[8];
    const float* out_b  = (const float*)d_in[9];
    const float* ffn_w1 = (const float*)d_in[10];
    const float* ffn_b1 = (const float*)d_in[11];
    const float* ffn_w2 = (const float*)d_in[12];
    const float* ffn_b2 = (const float*)d_in[13];
    const float* ln1_g  = (const float*)d_in[14];
    const float* ln1_b  = (const float*)d_in[15];
    const float* ln2_g  = (const float*)d_in[16];
    const float* ln2_b  = (const float*)d_in[17];
    const float* cls_w1 = (const float*)d_in[18];
    const float* cls_b1 = (const float*)d_in[19];
    const float* cls_w2 = (const float*)d_in[20];
    const float* cls_b2 = (const float*)d_in[21];
    const float* fp_w   = (const float*)d_in[22];
    const float* fp_b   = (const float*)d_in[23];

    const int B = in_sizes[0] / D;
    const size_t SMEM = (size_t)(TOK * LDA + TOK * LDB) * sizeof(float);

    cudaFuncSetAttribute(fusion_head_kernel,
                         cudaFuncAttributeMaxDynamicSharedMemorySize, (int)SMEM);

    repack_kernel<<<(PK_TOTAL + 255) / 256, 256>>>(
        Wp, Wt, in_w, out_w, ffn_w1, ffn_w2);

    const int grid = (B + ROWS - 1) / ROWS;
    fusion_head_kernel<<<grid, THREADS, SMEM>>>(
        perc, tech, bp, bt, in_b, out_b,
        ffn_b1, ffn_b2, ln1_g, ln1_b, ln2_g, ln2_b,
        cls_w1, cls_b1, cls_w2, cls_b2, fp_w, fp_b,
        (float*)d_out, B);
}

// round 11
// speedup vs baseline: 1.0011x; 1.0011x over previous
#include <cuda_runtime.h>
#include <cuda_bf16.h>
#include <math.h>

// FusionHead fully fused, fp32 + packed f32x2 FMA.
// R7: weight repacking. A per-launch repack kernel rewrites the five big GEMM
// stage weights into per-(warp,k-iter) consumption order so every weight
// LDG.128's four lane addresses are contiguous 64B (1 wavefront instead of 4).
// R5 was L1-bound at 89.5% with fma 43.3% because each weight load touched 4
// cache lines 4608B apart.

#define D 192
#define ROWS 16           // batch rows per CTA
#define TOK 32            // token rows per CTA
#define THREADS 256
#define LDA 196           // SA pitch (words): /4 = 49 (odd) -> conflict-free
#define LDB 580           // SB pitch (words): /4 = 145 (odd)

// packed weight segments (float4 units)
#define PK_WP   0
#define PK_WT   9216
#define PK_IN   18432
#define PK_OUT  46080
#define PK_F1   55296
#define PK_F2   73728
#define PK_TOTAL 92160    // 1.47 MB

__device__ float4 g_pack[PK_TOTAL];

typedef unsigned long long u64;

__device__ __forceinline__ void fma2(u64 &d, const u64 a, const u64 b) {
    asm("fma.rn.f32x2 %0, %1, %2, %0;" : "+l"(d) : "l"(a), "l"(b));
}
__device__ __forceinline__ float hsum2(const u64 v) {
    float lo, hi;
    asm("mov.b64 {%0, %1}, %2;" : "=f"(lo), "=f"(hi) : "l"(v));
    return lo + hi;
}
__device__ __forceinline__ u64 pack2(const float lo, const float hi) {
    u64 r;
    asm("mov.b64 %0, {%1, %2};" : "=l"(r) : "f"(lo), "f"(hi));
    return r;
}

// ---------------------------------------------------------------------------
// Repack kernel: g_pack[(pw*K4 + k)*24 + j*4 + cs] = W[c][4k..4k+3],
//   c = pw*24 + cs*6 + j   (pw = pass*8 + warp; pass block = 192 cols)
// ---------------------------------------------------------------------------
__global__ void repack_kernel(
    const float* __restrict__ Wp, const float* __restrict__ Wt,
    const float* __restrict__ in_w, const float* __restrict__ out_w,
    const float* __restrict__ ffn_w1, const float* __restrict__ ffn_w2)
{
    const int i = blockIdx.x * blockDim.x + threadIdx.x;
    if (i >= PK_TOTAL) return;
    const float* src;
    int K4, rel;
    if      (i < PK_WT)  { src = Wp;     K4 = 48; rel = i - PK_WP;  }
    else if (i < PK_IN)  { src = Wt;     K4 = 48; rel = i - PK_WT;  }
    else if (i < PK_OUT) { src = in_w;   K4 = 48; rel = i - PK_IN;  }
    else if (i < PK_F1)  { src = out_w;  K4 = 48; rel = i - PK_OUT; }
    else if (i < PK_F2)  { src = ffn_w1; K4 = 48; rel = i - PK_F1;  }
    else                 { src = ffn_w2; K4 = 96; rel = i - PK_F2;  }
    const int t  = rel % 24;
    const int cs = t & 3, j = t >> 2;
    const int rk = rel / 24;
    const int k  = rk % K4;
    const int pw = rk / K4;
    const int c  = pw * 24 + cs * 6 + j;
    g_pack[i] = reinterpret_cast<const float4*>(src)[(size_t)c * K4 + k];
}

// ---------------------------------------------------------------------------
// 4-row x 6-col register tile GEMM, packed weights.
//   pw01/pw23: packed weight base for this (pass,warp): g_pack + seg + pw*K4*24
//   rows {rg, rg+8, rg+16, rg+24}; cols c0..c0+? (c0 = cb + warp*24 + cs*6)
// ---------------------------------------------------------------------------
template<int K4, bool RELU, bool DUAL, bool RES>
__device__ __forceinline__ void gemm_tile(
    const float4* __restrict__ pw01, const float4* __restrict__ pw23,
    const float* __restrict__ b01, const float* __restrict__ b23,
    const float* __restrict__ Asm, int ldaw,
    float* __restrict__ Osm, int ldow,
    const float* __restrict__ Rsm, int ldrw,
    int c0, int cs, int rg)
{
    u64 acc[4][6];
    #pragma unroll
    for (int i = 0; i < 4; i++)
        #pragma unroll
        for (int j = 0; j < 6; j++) acc[i][j] = 0ULL;

    const float4* __restrict__ a0 = reinterpret_cast<const float4*>(Asm + rg * ldaw);
    const float4* __restrict__ a1 = reinterpret_cast<const float4*>(Asm + (rg + 8) * ldaw);
    const float4* __restrict__ a2 = reinterpret_cast<const float4*>(Asm + (rg + 16) * ldaw);
    const float4* __restrict__ a3 = reinterpret_cast<const float4*>(Asm + (rg + 24) * ldaw);

    #pragma unroll 2
    for (int k = 0; k < K4; k++) {
        const float4 av0 = a0[k], av1 = a1[k], av2 = a2[k], av3 = a3[k];
        const u64 lo0 = pack2(av0.x, av0.y), hi0 = pack2(av0.z, av0.w);
        const u64 lo1 = pack2(av1.x, av1.y), hi1 = pack2(av1.z, av1.w);
        const u64 lo2 = pack2(av2.x, av2.y), hi2 = pack2(av2.z, av2.w);
        const u64 lo3 = pack2(av3.x, av3.y), hi3 = pack2(av3.z, av3.w);
        const int kb = k * 24 + cs;
        #pragma unroll
        for (int j = 0; j < 6; j++) {
            const float4 w = pw01[kb + j * 4];
            const u64 wlo = pack2(w.x, w.y), whi = pack2(w.z, w.w);
            fma2(acc[0][j], lo0, wlo); fma2(acc[0][j], hi0, whi);
            fma2(acc[1][j], lo1, wlo); fma2(acc[1][j], hi1, whi);
            u64 wlo2, whi2;
            if (DUAL) {
                const float4 w2 = pw23[kb + j * 4];
                wlo2 = pack2(w2.x, w2.y); whi2 = pack2(w2.z, w2.w);
            } else { wlo2 = wlo; whi2 = whi; }
            fma2(acc[2][j], lo2, wlo2); fma2(acc[2][j], hi2, whi2);
            fma2(acc[3][j], lo3, wlo2); fma2(acc[3][j], hi3, whi2);
        }
    }

    #pragma unroll
    for (int j = 0; j < 6; j++) {
        const int c = c0 + j;
        float v0 = hsum2(acc[0][j]) + b01[c];
        float v1 = hsum2(acc[1][j]) + b01[c];
        float v2 = hsum2(acc[2][j]) + b23[c];
        float v3 = hsum2(acc[3][j]) + b23[c];
        if (RES) {
            v0 += Rsm[rg * ldrw + c];
            v1 += Rsm[(rg + 8) * ldrw + c];
            v2 += Rsm[(rg + 16) * ldrw + c];
            v3 += Rsm[(rg + 24) * ldrw + c];
        }
        if (RELU) {
            v0 = fmaxf(v0, 0.f); v1 = fmaxf(v1, 0.f);
            v2 = fmaxf(v2, 0.f); v3 = fmaxf(v3, 0.f);
        }
        Osm[rg * ldow + c]        = v0;
        Osm[(rg + 8) * ldow + c]  = v1;
        Osm[(rg + 16) * ldow + c] = v2;
        Osm[(rg + 24) * ldow + c] = v3;
    }
}

// Head-stage GEMM (small): one thread, C cols for one activation row.
template<int C, int K, bool RELU>
__device__ __forceinline__ void gemm_b(
    const float* __restrict__ Wc, const float* __restrict__ biasc,
    const float* __restrict__ Arow,
    float* __restrict__ Orow)
{
    u64 acc[C];
    #pragma unroll
    for (int c = 0; c < C; c++) acc[c] = 0ULL;
    const float4* __restrict__ a4 = reinterpret_cast<const float4*>(Arow);
    #pragma unroll 2
    for (int k = 0; k < (K >> 2); k++) {
        const float4 av = a4[k];
        const u64 alo = pack2(av.x, av.y);
        const u64 ahi = pack2(av.z, av.w);
        #pragma unroll
        for (int c = 0; c < C; c++) {
            const float4 wv = *reinterpret_cast<const float4*>(Wc + c * K + (k << 2));
            fma2(acc[c], alo, pack2(wv.x, wv.y));
            fma2(acc[c], ahi, pack2(wv.z, wv.w));
        }
    }
    #pragma unroll
    for (int c = 0; c < C; c++) {
        float v = hsum2(acc[c]) + biasc[c];
        if (RELU) v = fmaxf(v, 0.f);
        Orow[c] = v;
    }
}

__device__ __forceinline__ void layernorm_rows(
    const float* __restrict__ src, int lds,
    float* __restrict__ dst, int ldd,
    const float* __restrict__ g, const float* __restrict__ b,
    int tid)
{
    const int warp = tid >> 5, lane = tid & 31;
    for (int tr = warp; tr < TOK; tr += 8) {
        const float* x = src + tr * lds;
        float v[6], s = 0.f, sq = 0.f;
        #pragma unroll
        for (int j = 0; j < 6; j++) {
            v[j] = x[lane + 32 * j];
            s += v[j];
            sq += v[j] * v[j];
        }
        #pragma unroll
        for (int o = 16; o; o >>= 1) {
            s  += __shfl_xor_sync(0xffffffffu, s,  o);
            sq += __shfl_xor_sync(0xffffffffu, sq, o);
        }
        const float mean = s * (1.f / 192.f);
        const float var  = sq * (1.f / 192.f) - mean * mean;
        const float rs   = rsqrtf(var + 1e-5f);
        #pragma unroll
        for (int j = 0; j < 6; j++) {
            const int c = lane + 32 * j;
            dst[tr * ldd + c] = (v[j] - mean) * rs * g[c] + b[c];
        }
    }
}

__global__ __launch_bounds__(THREADS, 2)
void fusion_head_kernel(
    const float* __restrict__ perc, const float* __restrict__ tech,
    const float* __restrict__ bp,   const float* __restrict__ bt,
    const float* __restrict__ in_b,
    const float* __restrict__ out_b,
    const float* __restrict__ ffn_b1, const float* __restrict__ ffn_b2,
    const float* __restrict__ ln1_g, const float* __restrict__ ln1_b,
    const float* __restrict__ ln2_g, const float* __restrict__ ln2_b,
    const float* __restrict__ cls_w1, const float* __restrict__ cls_b1,
    const float* __restrict__ cls_w2, const float* __restrict__ cls_b2,
    const float* __restrict__ fp_w,   const float* __restrict__ fp_b,
    float* __restrict__ out, int B)
{
    extern __shared__ float smem[];
    float* SA = smem;                 // [32][LDA] residual / LN stream
    float* SB = smem + TOK * LDA;     // [32][LDB] scratch

    const int tid  = threadIdx.x;
    const int lane = tid & 31;
    const int warp = tid >> 5;
    const int cs   = lane >> 3;       // column subset 0..3
    const int rg   = lane & 7;        // row group 0..7
    const int cbase = warp * 24 + cs * 6;
    const int block0 = blockIdx.x * ROWS;

    // ---- stage 0: stage inputs into SB[tr][0:192] (tr<16: perc, else tech) --
    for (int i = tid; i < TOK * 48; i += THREADS) {
        const int tr = i / 48, k4 = i % 48;
        const int r = (tr < ROWS) ? tr : (tr - ROWS);
        int gr = block0 + r;
        if (gr >= B) gr = B - 1;
        const float* src = (tr < ROWS) ? (perc + (size_t)gr * D)
                                       : (tech + (size_t)gr * D);
        reinterpret_cast<float4*>(SB + tr * LDB)[k4] =
            reinterpret_cast<const float4*>(src)[k4];
    }
    __syncthreads();

    // ---- stage 1: input projections -> SA (rows 0-15: Wp, rows 16-31: Wt) --
    gemm_tile<48, false, true, false>(
        g_pack + PK_WP + warp * 48 * 24, g_pack + PK_WT + warp * 48 * 24,
        bp, bt, SB, LDB, SA, LDA, nullptr, 0, cbase, cs, rg);
    __syncthreads();

    // ---- stage 2: packed QKV -> SB[tr][0:576] (3 column passes) ------------
    #pragma unroll
    for (int p = 0; p < 3; p++) {
        const float4* pw = g_pack + PK_IN + (size_t)(p * 8 + warp) * 48 * 24;
        gemm_tile<48, false, false, false>(pw, pw, in_b, in_b,
                                           SA, LDA, SB, LDB, nullptr, 0,
                                           p * 192 + cbase, cs, rg);
    }
    __syncthreads();

    // ---- stage 3: 2-token, 3-head attention; ctx overwrites q slots --------
    if (tid < ROWS * 6) {
        const int r = tid / 6, rem = tid % 6;
        const int t = rem & 1, h = rem >> 1;
        const float* q  = SB + (t * ROWS + r) * LDB + h * 64;
        const float* k0 = SB + r * LDB + 192 + h * 64;
        const float* k1 = SB + (ROWS + r) * LDB + 192 + h * 64;
        const float* v0 = SB + r * LDB + 384 + h * 64;
        const float* v1 = SB + (ROWS + r) * LDB + 384 + h * 64;
        float s0 = 0.f, s1 = 0.f;
        #pragma unroll 8
        for (int d = 0; d < 64; d++) {
            const float qd = q[d];
            s0 += qd * k0[d];
            s1 += qd * k1[d];
        }
        s0 *= 0.125f; s1 *= 0.125f;
        const float m = fmaxf(s0, s1);
        const float e0 = expf(s0 - m), e1 = expf(s1 - m);
        const float inv = 1.f / (e0 + e1);
        const float a0 = e0 * inv, a1 = e1 * inv;
        float* ctx = SB + (t * ROWS + r) * LDB + h * 64;  // q slot
        #pragma unroll 8
        for (int d = 0; d < 64; d++) ctx[d] = a0 * v0[d] + a1 * v1[d];
    }
    __syncthreads();

    // ---- stage 4: out-proj + residual(SA) -> SB[tr][384:576] ---------------
    {
        const float4* pw = g_pack + PK_OUT + warp * 48 * 24;
        gemm_tile<48, false, false, true>(pw, pw, out_b, out_b,
                                          SB, LDB, SB + 384, LDB, SA, LDA,
                                          cbase, cs, rg);
    }
    __syncthreads();

    // ---- stage 5: LN1 -> SA ------------------------------------------------
    layernorm_rows(SB + 384, LDB, SA, LDA, ln1_g, ln1_b, tid);
    __syncthreads();

    // ---- stage 6: FFN up + ReLU -> SB[tr][0:384] (2 passes) ----------------
    #pragma unroll
    for (int p = 0; p < 2; p++) {
        const float4* pw = g_pack + PK_F1 + (size_t)(p * 8 + warp) * 48 * 24;
        gemm_tile<48, true, false, false>(pw, pw, ffn_b1, ffn_b1,
                                          SA, LDA, SB, LDB, nullptr, 0,
                                          p * 192 + cbase, cs, rg);
    }
    __syncthreads();

    // ---- stage 7: FFN down (K=384) + residual(SA) -> SB[tr][384:576] -------
    {
        const float4* pw = g_pack + PK_F2 + warp * 96 * 24;
        gemm_tile<96, false, false, true>(pw, pw, ffn_b2, ffn_b2,
                                          SB, LDB, SB + 384, LDB, SA, LDA,
                                          cbase, cs, rg);
    }
    __syncthreads();

    // ---- stage 8: LN2 -> SA ------------------------------------------------
    layernorm_rows(SB + 384, LDB, SA, LDA, ln2_g, ln2_b, tid);
    __syncthreads();

    // ---- stage 9: z = mean over 2 tokens -> SB[r][384:576] -----------------
    for (int i = tid; i < ROWS * 48; i += THREADS) {
        const int r = i / 48, k4 = i % 48;
        const float4 x0 = reinterpret_cast<const float4*>(SA + r * LDA)[k4];
        const float4 x1 = reinterpret_cast<const float4*>(SA + (ROWS + r) * LDA)[k4];
        float4 z;
        z.x = 0.5f * (x0.x + x1.x);
        z.y = 0.5f * (x0.y + x1.y);
        z.z = 0.5f * (x0.z + x1.z);
        z.w = 0.5f * (x0.w + x1.w);
        reinterpret_cast<float4*>(SB + r * LDB + 384)[k4] = z;
    }
    __syncthreads();

    // ---- stage 10: heads. row = lane&15, col-half = lane>>4 ----------------
    {
        const int r  = lane & 15;
        const int hf = lane >> 4;
        const float* zrow = SB + r * LDB + 384;
        // cls hidden (relu): 192 cols -> SB[r][0:192]
        {
            const int c0 = warp * 24 + hf * 12;
            gemm_b<12, 192, true>(cls_w1 + c0 * 192, cls_b1 + c0,
                                  zrow, SB + r * LDB + c0);
        }
        // fingerprint: 128 cols -> SB[r][192:320]
        {
            const int c0 = warp * 16 + hf * 8;
            gemm_b<8, 192, false>(fp_w + c0 * 192, fp_b + c0,
                                  zrow, SB + r * LDB + 192 + c0);
        }
    }
    __syncthreads();

    // ---- stage 11: cls logits + sigmoid -> out[j*B + row] ------------------
    if (tid < ROWS * 3) {
        const int r = tid / 3, j = tid % 3;
        const int gr = block0 + r;
        if (gr < B) {
            const float* hrow = SB + r * LDB;
            const float* w = cls_w2 + j * D;
            float s = cls_b2[j];
            #pragma unroll 8
            for (int k = 0; k < D; k++) s += hrow[k] * w[k];
            out[(size_t)j * B + gr] = 1.f / (1.f + expf(-s));
        }
    }

    // ---- stage 12: fingerprint L2-normalize -> out[3B + row*128 + c] -------
    {
        #pragma unroll
        for (int rr = 0; rr < 2; rr++) {
            const int r = warp * 2 + rr;
            const int gr = block0 + r;
            const float* f = SB + r * LDB + 192;
            float v[4], sq = 0.f;
            #pragma unroll
            for (int j = 0; j < 4; j++) {
                v[j] = f[lane + 32 * j];
                sq += v[j] * v[j];
            }
            #pragma unroll
            for (int o = 16; o; o >>= 1)
                sq += __shfl_xor_sync(0xffffffffu, sq, o);
            const float inv = 1.f / fmaxf(sqrtf(sq), 1e-12f);
            if (gr < B) {
                float* o = out + (size_t)3 * B + (size_t)gr * 128;
                #pragma unroll
                for (int j = 0; j < 4; j++) o[lane + 32 * j] = v[j] * inv;
            }
        }
    }
}

extern "C" void kernel_launch(void* const* d_in, const int* in_sizes, int n_in,
                              void* d_out, int out_size)
{
    const float* perc   = (const float*)d_in[0];
    const float* tech   = (const float*)d_in[1];
    const float* Wp     = (const float*)d_in[2];
    const float* bp     = (const float*)d_in[3];
    const float* Wt     = (const float*)d_in[4];
    const float* bt     = (const float*)d_in[5];
    const float* in_w   = (const float*)d_in[6];
    const float* in_b   = (const float*)d_in[7];
    const float* out_w  = (const float*)d_in[8];
    const float* out_b  = (const float*)d_in[9];
    const float* ffn_w1 = (const float*)d_in[10];
    const float* ffn_b1 = (const float*)d_in[11];
    const float* ffn_w2 = (const float*)d_in[12];
    const float* ffn_b2 = (const float*)d_in[13];
    const float* ln1_g  = (const float*)d_in[14];
    const float* ln1_b  = (const float*)d_in[15];
    const float* ln2_g  = (const float*)d_in[16];
    const float* ln2_b  = (const float*)d_in[17];
    const float* cls_w1 = (const float*)d_in[18];
    const float* cls_b1 = (const float*)d_in[19];
    const float* cls_w2 = (const float*)d_in[20];
    const float* cls_b2 = (const float*)d_in[21];
    const float* fp_w   = (const float*)d_in[22];
    const float* fp_b   = (const float*)d_in[23];

    const int B = in_sizes[0] / D;
    const size_t SMEM = (size_t)(TOK * LDA + TOK * LDB) * sizeof(float);

    cudaFuncSetAttribute(fusion_head_kernel,
                         cudaFuncAttributeMaxDynamicSharedMemorySize, (int)SMEM);

    repack_kernel<<<(PK_TOTAL + 255) / 256, 256>>>(
        Wp, Wt, in_w, out_w, ffn_w1, ffn_w2);

    const int grid = (B + ROWS - 1) / ROWS;
    fusion_head_kernel<<<grid, THREADS, SMEM>>>(
        perc, tech, bp, bt, in_b, out_b,
        ffn_b1, ffn_b2, ln1_g, ln1_b, ln2_g, ln2_b,
        cls_w1, cls_b1, cls_w2, cls_b2, fp_w, fp_b,
        (float*)d_out, B);
}